// round 10
// baseline (speedup 1.0000x reference)
#include <cuda_runtime.h>
#include <cuda_fp16.h>
#include <cstdint>

// ---------------------------------------------------------------------------
// RBF layer: out[b,l] = exp(-gamma * max(||x_b||^2 + ||lm_l||^2 - 2 x_b.lm_l, 0))
// B=8192, L=2048, D=256, gamma = 1/256.
// R10: legacy mma.sync path is throughput-ceilinged (~280 TF/s); maximize feed:
// fp16 accumulators (32 regs) -> 3 CTAs/SM (24 warps), proven R2/R5 mainloop,
// 2-stage cp.async, 32x64 warp tiles, exact fp32 norms, ex2 epilogue.
// ---------------------------------------------------------------------------

#define BB 8192
#define LL 2048
#define DD 256
#define TM 128
#define TN 128

// smem: 2 stages x (A 16KB + B 16KB) + l2 tile
#define STAGE_BYTES 32768
#define SMEM_L2     65536
#define SMEM_SIZE   66048

// ---------------- device scratch (static: no allocation APIs) --------------
__device__ __align__(16) __half g_xh[BB * DD];
__device__ __align__(16) __half g_lh[LL * DD];
__device__ float g_x2[BB];
__device__ float g_l2[LL];

// ---------------- helpers ---------------------------------------------------
__device__ __forceinline__ uint32_t smem_u32(const void* p) {
    uint32_t a;
    asm("{ .reg .u64 t; cvta.to.shared.u64 t, %1; cvt.u32.u64 %0, t; }"
        : "=r"(a) : "l"(p));
    return a;
}

__device__ __forceinline__ float fast_ex2(float x) {
    float y;
    asm("ex2.approx.ftz.f32 %0, %1;" : "=f"(y) : "f"(x));
    return y;
}

#define CP_ASYNC_16(sa, ga)                                               \
    asm volatile("cp.async.cg.shared.global [%0], [%1], 16;" ::           \
                 "r"(sa), "l"(ga))
#define CP_COMMIT() asm volatile("cp.async.commit_group;" ::: "memory")
#define CP_WAIT0()  asm volatile("cp.async.wait_group 0;" ::: "memory")

#define LDSM4(r0, r1, r2, r3, addr)                                        \
    asm volatile("ldmatrix.sync.aligned.m8n8.x4.shared.b16 {%0,%1,%2,%3}, [%4];" \
                 : "=r"(r0), "=r"(r1), "=r"(r2), "=r"(r3) : "r"(addr))

// fp16-accumulate MMA: D(2xb32 = 4 halves) = A*B + D
#define MMA16816H(d, a0, a1, a2, a3, b0, b1)                               \
    asm volatile(                                                          \
        "mma.sync.aligned.m16n8k16.row.col.f16.f16.f16.f16 "               \
        "{%0,%1}, {%2,%3,%4,%5}, {%6,%7}, {%0,%1};"                        \
        : "+r"((d)[0]), "+r"((d)[1])                                       \
        : "r"(a0), "r"(a1), "r"(a2), "r"(a3), "r"(b0), "r"(b1))

// ---------------- prep: fp32 -> fp16 + exact fp32 row norms ----------------
__global__ void __launch_bounds__(256) rbf_prep(const float* __restrict__ x,
                                                const float* __restrict__ lm) {
    int warp = threadIdx.x >> 5, lane = threadIdx.x & 31;
    int row = blockIdx.x * 8 + warp;
    const float* src;
    __half* dst;
    float* nrm;
    if (row < BB) {
        src = x + (size_t)row * DD;
        dst = g_xh + (size_t)row * DD;
        nrm = g_x2 + row;
    } else {
        int r = row - BB;
        if (r >= LL) return;
        src = lm + (size_t)r * DD;
        dst = g_lh + (size_t)r * DD;
        nrm = g_l2 + r;
    }
    float4 a = *(const float4*)(src + lane * 8);
    float4 b = *(const float4*)(src + lane * 8 + 4);
    float s = a.x * a.x + a.y * a.y + a.z * a.z + a.w * a.w +
              b.x * b.x + b.y * b.y + b.z * b.z + b.w * b.w;
    __half2 h0 = __floats2half2_rn(a.x, a.y);
    __half2 h1 = __floats2half2_rn(a.z, a.w);
    __half2 h2 = __floats2half2_rn(b.x, b.y);
    __half2 h3 = __floats2half2_rn(b.z, b.w);
    uint4 u;
    u.x = reinterpret_cast<uint32_t&>(h0);
    u.y = reinterpret_cast<uint32_t&>(h1);
    u.z = reinterpret_cast<uint32_t&>(h2);
    u.w = reinterpret_cast<uint32_t&>(h3);
    *reinterpret_cast<uint4*>(dst + lane * 8) = u;
#pragma unroll
    for (int o = 16; o; o >>= 1) s += __shfl_xor_sync(0xffffffffu, s, o);
    if (lane == 0) *nrm = s;
}

// ---------------- main GEMM + exp epilogue ----------------------------------
__global__ void __launch_bounds__(256, 3) rbf_main(float* __restrict__ out) {
    extern __shared__ char smem[];
    uint32_t sb = smem_u32(smem);
    int tid = threadIdx.x, wid = tid >> 5, lane = tid & 31;
    int m0 = blockIdx.y * TM;
    int n0 = blockIdx.x * TN;
    int wm = (wid & 3) * 32;   // warp M offset within tile (4 warps in M)
    int wn = (wid >> 2) * 64;  // warp N offset within tile (2 warps in N)

    // landmark norm tile -> smem
    if (tid < TN)
        reinterpret_cast<float*>(smem + SMEM_L2)[tid] = g_l2[n0 + tid];

    // ---- cp.async prefetch of one K-chunk (64 halves) into stage kc&1 ----
    auto prefetch = [&](int kc) {
        int stage = kc & 1;
        uint32_t sA = sb + stage * STAGE_BYTES;
        uint32_t sB = sA + 16384;
        int koff = kc * 64;
#pragma unroll
        for (int j = 0; j < 4; j++) {
            int idx = tid + j * 256;       // 0..1023
            int r = idx >> 3, c = idx & 7; // row, 16B-chunk
            uint32_t soff = (uint32_t)(r * 128 + ((c * 16) ^ ((r & 7) << 4)));
            const __half* ga = g_xh + (size_t)(m0 + r) * DD + koff + c * 8;
            const __half* gb = g_lh + (size_t)(n0 + r) * DD + koff + c * 8;
            CP_ASYNC_16(sA + soff,
                        (unsigned long long)__cvta_generic_to_global((void*)ga));
            CP_ASYNC_16(sB + soff,
                        (unsigned long long)__cvta_generic_to_global((void*)gb));
        }
        CP_COMMIT();
    };

    // persistent fp16 accumulators: 2 m-tiles x 8 n-tiles x 2 b32 = 32 regs
    uint32_t hacc[2][8][2];
#pragma unroll
    for (int mt = 0; mt < 2; mt++)
#pragma unroll
        for (int nt = 0; nt < 8; nt++) {
            hacc[mt][nt][0] = 0u;
            hacc[mt][nt][1] = 0u;
        }

    // lane-level smem addressing (constant across k-steps)
    int la = lane & 15;
    uint32_t xm = (uint32_t)((lane & 7) << 4);
    uint32_t kblA = (uint32_t)(((lane >> 4) & 1) << 4);  // k8 select for A
    int rb = (lane & 7) + (((lane >> 4) & 1) << 3);      // B row within 16
    uint32_t kblB = (uint32_t)(((lane >> 3) & 1) << 4);  // k8 select for B

    prefetch(0);

#pragma unroll
    for (int kc = 0; kc < 4; kc++) {
        CP_WAIT0();
        __syncthreads();
        // safe with 2 stages: every warp passed the barrier after finishing
        // compute on the stage this prefetch overwrites
        if (kc < 3) prefetch(kc + 1);

        int stage = kc & 1;
        uint32_t sA = sb + stage * STAGE_BYTES;
        uint32_t sB = sA + 16384;
        uint32_t aRow0 = sA + (uint32_t)((wm + la) * 128);
        uint32_t aRow1 = aRow0 + 16 * 128;
        uint32_t bRow = sB + (uint32_t)((wn + rb) * 128);

#pragma unroll
        for (int ks = 0; ks < 4; ks++) {
            uint32_t kb = (uint32_t)(ks * 32);
            uint32_t a0[4], a1[4];
            uint32_t adA = (kb + kblA) ^ xm;
            LDSM4(a0[0], a0[1], a0[2], a0[3], aRow0 + adA);
            LDSM4(a1[0], a1[1], a1[2], a1[3], aRow1 + adA);
            uint32_t adB = (kb + kblB) ^ xm;
#pragma unroll
            for (int ntp = 0; ntp < 4; ntp++) {
                uint32_t b0, b1, b2, b3;
                LDSM4(b0, b1, b2, b3, bRow + (uint32_t)(ntp * 2048) + adB);
                MMA16816H(hacc[0][2 * ntp], a0[0], a0[1], a0[2], a0[3], b0, b1);
                MMA16816H(hacc[1][2 * ntp], a1[0], a1[1], a1[2], a1[3], b0, b1);
                MMA16816H(hacc[0][2 * ntp + 1], a0[0], a0[1], a0[2], a0[3],
                          b2, b3);
                MMA16816H(hacc[1][2 * ntp + 1], a1[0], a1[1], a1[2], a1[3],
                          b2, b3);
            }
        }
    }

    // ---- epilogue: ex2(C * max(x2 + l2 - 2*cross, 0)),  C = -log2(e)/256 ----
    const float* l2t = reinterpret_cast<const float*>(smem + SMEM_L2);
    const float C = -1.44269504088896f / 256.0f;
    int qr = lane >> 2, qc = (lane & 3) << 1;
#pragma unroll
    for (int mt = 0; mt < 2; mt++) {
#pragma unroll
        for (int p = 0; p < 2; p++) {
            int row = m0 + wm + mt * 16 + p * 8 + qr;
            float x2v = __ldg(&g_x2[row]);
            float* orow = out + (size_t)row * LL + n0 + wn;
#pragma unroll
            for (int nt = 0; nt < 8; nt++) {
                int col = nt * 8 + qc;
                float2 cr = __half22float2(
                    *reinterpret_cast<__half2*>(&hacc[mt][nt][p]));
                float d0 = fmaxf(x2v + l2t[wn + col] - 2.0f * cr.x, 0.0f);
                float d1 = fmaxf(x2v + l2t[wn + col + 1] - 2.0f * cr.y, 0.0f);
                float2 o;
                o.x = fast_ex2(C * d0);
                o.y = fast_ex2(C * d1);
                *reinterpret_cast<float2*>(orow + col) = o;
            }
        }
    }
}

// ---------------- launch ----------------------------------------------------
extern "C" void kernel_launch(void* const* d_in, const int* in_sizes, int n_in,
                              void* d_out, int out_size) {
    const float* x = (const float*)d_in[0];   // [8192, 256]
    const float* lm = (const float*)d_in[1];  // [2048, 256]
    float* out = (float*)d_out;               // [8192, 2048]

    cudaFuncSetAttribute(rbf_main, cudaFuncAttributeMaxDynamicSharedMemorySize,
                         SMEM_SIZE);

    rbf_prep<<<(BB + LL) / 8, 256>>>(x, lm);
    dim3 grid(LL / TN, BB / TM);  // (16, 64) = 1024 CTAs
    rbf_main<<<grid, 256, SMEM_SIZE>>>(out);
}

// round 12
// speedup vs baseline: 1.1115x; 1.1115x over previous
#include <cuda_runtime.h>
#include <cuda_fp16.h>
#include <cstdint>

// ---------------------------------------------------------------------------
// RBF layer: out[b,l] = exp(-gamma * max(||x_b||^2 + ||lm_l||^2 - 2 x_b.lm_l, 0))
// B=8192, L=2048, D=256, gamma = 1/256.
// R11: single fused kernel. Legacy mma.sync path is issue-rate ceilinged
// (~288 TF/s, rt=4cyc/SMSP); mainloop is at 96% of it, so recover the prep
// kernel + fp16-scratch round-trip instead: load fp32 tiles straight from L2,
// convert to fp16 inline (interleaved with MMAs at k-step granularity),
// accumulate exact fp32 row norms inline via octet shuffle reduce.
// fp16 HMMA accumulators (measured rel_err 8.4e-5), ex2 epilogue.
// ---------------------------------------------------------------------------

#define BB 8192
#define LL 2048
#define DD 256
#define TM 128
#define TN 128

// smem: 2 stages x (A 16KB + B 16KB) fp16 + l2 norms (512B) + x2 norms (512B)
#define STAGE_BYTES 32768
#define SMEM_L2     65536
#define SMEM_X2     66048
#define SMEM_SIZE   66560

// ---------------- helpers ---------------------------------------------------
__device__ __forceinline__ uint32_t smem_u32(const void* p) {
    uint32_t a;
    asm("{ .reg .u64 t; cvta.to.shared.u64 t, %1; cvt.u32.u64 %0, t; }"
        : "=r"(a) : "l"(p));
    return a;
}

__device__ __forceinline__ float fast_ex2(float x) {
    float y;
    asm("ex2.approx.ftz.f32 %0, %1;" : "=f"(y) : "f"(x));
    return y;
}

__device__ __forceinline__ uint4 cvt8(const float4& a, const float4& b) {
    __half2 h0 = __floats2half2_rn(a.x, a.y);
    __half2 h1 = __floats2half2_rn(a.z, a.w);
    __half2 h2 = __floats2half2_rn(b.x, b.y);
    __half2 h3 = __floats2half2_rn(b.z, b.w);
    uint4 u;
    u.x = reinterpret_cast<uint32_t&>(h0);
    u.y = reinterpret_cast<uint32_t&>(h1);
    u.z = reinterpret_cast<uint32_t&>(h2);
    u.w = reinterpret_cast<uint32_t&>(h3);
    return u;
}

__device__ __forceinline__ float sq8(const float4& a, const float4& b) {
    return a.x * a.x + a.y * a.y + a.z * a.z + a.w * a.w +
           b.x * b.x + b.y * b.y + b.z * b.z + b.w * b.w;
}

#define LDSM4(r0, r1, r2, r3, addr)                                        \
    asm volatile("ldmatrix.sync.aligned.m8n8.x4.shared.b16 {%0,%1,%2,%3}, [%4];" \
                 : "=r"(r0), "=r"(r1), "=r"(r2), "=r"(r3) : "r"(addr))

// fp16-accumulate MMA: D(2xb32 = 4 halves) = A*B + D
#define MMA16816H(d, a0, a1, a2, a3, b0, b1)                               \
    asm volatile(                                                          \
        "mma.sync.aligned.m16n8k16.row.col.f16.f16.f16.f16 "               \
        "{%0,%1}, {%2,%3,%4,%5}, {%6,%7}, {%0,%1};"                        \
        : "+r"((d)[0]), "+r"((d)[1])                                       \
        : "r"(a0), "r"(a1), "r"(a2), "r"(a3), "r"(b0), "r"(b1))

// ---------------- fused GEMM + norms + exp epilogue -------------------------
__global__ void __launch_bounds__(256, 2) rbf_fused(
    const float* __restrict__ x, const float* __restrict__ lm,
    float* __restrict__ out) {
    extern __shared__ char smem[];
    uint32_t sb = smem_u32(smem);
    int tid = threadIdx.x, wid = tid >> 5, lane = tid & 31;
    int m0 = blockIdx.y * TM;
    int n0 = blockIdx.x * TN;
    int wm = (wid & 3) * 32;   // warp M offset within tile (4 warps in M)
    int wn = (wid >> 2) * 64;  // warp N offset within tile (2 warps in N)

    // per-thread load mapping: row lr + j*32, column octet lc (8 floats)
    int lr = tid >> 3;               // 0..31
    int lc = tid & 7;                // 0..7
    uint32_t soffBase[4];
#pragma unroll
    for (int j = 0; j < 4; j++) {
        int r = lr + j * 32;
        soffBase[j] = (uint32_t)(r * 128 + ((lc * 16) ^ ((r & 7) << 4)));
    }

    float na[4] = {0.f, 0.f, 0.f, 0.f};  // x row-norm partials
    float nb[4] = {0.f, 0.f, 0.f, 0.f};  // lm row-norm partials

    // one (row-block j, chunk kc) load+convert+store piece
    auto piece = [&](int kc, int j) {
        int koff = kc * 64 + lc * 8;
        int r = lr + j * 32;
        uint32_t stg = sb + (uint32_t)((kc & 1) * STAGE_BYTES);
        const float4* ga =
            reinterpret_cast<const float4*>(x + (size_t)(m0 + r) * DD + koff);
        float4 a0 = ga[0], a1 = ga[1];
        const float4* gb =
            reinterpret_cast<const float4*>(lm + (size_t)(n0 + r) * DD + koff);
        float4 b0 = gb[0], b1 = gb[1];
        na[j] += sq8(a0, a1);
        nb[j] += sq8(b0, b1);
        *reinterpret_cast<uint4*>(smem + (stg - sb) + soffBase[j]) = cvt8(a0, a1);
        *reinterpret_cast<uint4*>(smem + (stg - sb) + 16384 + soffBase[j]) =
            cvt8(b0, b1);
    };

    // persistent fp16 accumulators: 2 m-tiles x 8 n-tiles x 2 b32 = 32 regs
    uint32_t hacc[2][8][2];
#pragma unroll
    for (int mt = 0; mt < 2; mt++)
#pragma unroll
        for (int nt = 0; nt < 8; nt++) {
            hacc[mt][nt][0] = 0u;
            hacc[mt][nt][1] = 0u;
        }

    // lane-level smem addressing for MMA phase (constant across k-steps)
    int la = lane & 15;
    uint32_t xm = (uint32_t)((lane & 7) << 4);
    uint32_t kblA = (uint32_t)(((lane >> 4) & 1) << 4);  // k8 select for A
    int rb = (lane & 7) + (((lane >> 4) & 1) << 3);      // B row within 16
    uint32_t kblB = (uint32_t)(((lane >> 3) & 1) << 4);  // k8 select for B

    // prologue: stage 0
#pragma unroll
    for (int j = 0; j < 4; j++) piece(0, j);
    __syncthreads();

#pragma unroll
    for (int kc = 0; kc < 4; kc++) {
        uint32_t sA = sb + (uint32_t)((kc & 1) * STAGE_BYTES);
        uint32_t sB = sA + 16384;
        uint32_t aRow0 = sA + (uint32_t)((wm + la) * 128);
        uint32_t aRow1 = aRow0 + 16 * 128;
        uint32_t bRow = sB + (uint32_t)((wn + rb) * 128);

#pragma unroll
        for (int ks = 0; ks < 4; ks++) {
            // interleave one convert piece of chunk kc+1 with this k-step's
            // MMAs: LDGs issue here, results consumed after the MMA block
            // (plain loads schedule early; MMA issue hides L2 latency)
            if (kc < 3) piece(kc + 1, ks);

            uint32_t kb = (uint32_t)(ks * 32);
            uint32_t a0[4], a1[4];
            uint32_t adA = (kb + kblA) ^ xm;
            LDSM4(a0[0], a0[1], a0[2], a0[3], aRow0 + adA);
            LDSM4(a1[0], a1[1], a1[2], a1[3], aRow1 + adA);
            uint32_t adB = (kb + kblB) ^ xm;
#pragma unroll
            for (int ntp = 0; ntp < 4; ntp++) {
                uint32_t b0, b1, b2, b3;
                LDSM4(b0, b1, b2, b3, bRow + (uint32_t)(ntp * 2048) + adB);
                MMA16816H(hacc[0][2 * ntp], a0[0], a0[1], a0[2], a0[3], b0, b1);
                MMA16816H(hacc[1][2 * ntp], a1[0], a1[1], a1[2], a1[3], b0, b1);
                MMA16816H(hacc[0][2 * ntp + 1], a0[0], a0[1], a0[2], a0[3],
                          b2, b3);
                MMA16816H(hacc[1][2 * ntp + 1], a1[0], a1[1], a1[2], a1[3],
                          b2, b3);
            }
        }
        __syncthreads();
    }

    // ---- finalize norms: reduce over column octet (8 consecutive lanes) ----
    {
        float* x2s = reinterpret_cast<float*>(smem + SMEM_X2);
        float* l2s = reinterpret_cast<float*>(smem + SMEM_L2);
#pragma unroll
        for (int j = 0; j < 4; j++) {
            float va = na[j], vb = nb[j];
#pragma unroll
            for (int o = 1; o < 8; o <<= 1) {
                va += __shfl_xor_sync(0xffffffffu, va, o);
                vb += __shfl_xor_sync(0xffffffffu, vb, o);
            }
            if (lc == 0) {
                x2s[lr + j * 32] = va;
                l2s[lr + j * 32] = vb;
            }
        }
    }
    __syncthreads();

    // ---- epilogue: ex2(C * max(x2 + l2 - 2*cross, 0)),  C = -log2(e)/256 ----
    const float* l2t = reinterpret_cast<const float*>(smem + SMEM_L2);
    const float* x2t = reinterpret_cast<const float*>(smem + SMEM_X2);
    const float C = -1.44269504088896f / 256.0f;
    int qr = lane >> 2, qc = (lane & 3) << 1;
#pragma unroll
    for (int mt = 0; mt < 2; mt++) {
#pragma unroll
        for (int p = 0; p < 2; p++) {
            int rloc = wm + mt * 16 + p * 8 + qr;
            float x2v = x2t[rloc];
            float* orow = out + (size_t)(m0 + rloc) * LL + n0 + wn;
#pragma unroll
            for (int nt = 0; nt < 8; nt++) {
                int col = nt * 8 + qc;
                float2 cr = __half22float2(
                    *reinterpret_cast<__half2*>(&hacc[mt][nt][p]));
                float d0 = fmaxf(x2v + l2t[wn + col] - 2.0f * cr.x, 0.0f);
                float d1 = fmaxf(x2v + l2t[wn + col + 1] - 2.0f * cr.y, 0.0f);
                float2 o;
                o.x = fast_ex2(C * d0);
                o.y = fast_ex2(C * d1);
                *reinterpret_cast<float2*>(orow + col) = o;
            }
        }
    }
}

// ---------------- launch ----------------------------------------------------
extern "C" void kernel_launch(void* const* d_in, const int* in_sizes, int n_in,
                              void* d_out, int out_size) {
    const float* x = (const float*)d_in[0];   // [8192, 256]
    const float* lm = (const float*)d_in[1];  // [2048, 256]
    float* out = (float*)d_out;               // [8192, 2048]

    cudaFuncSetAttribute(rbf_fused, cudaFuncAttributeMaxDynamicSharedMemorySize,
                         SMEM_SIZE);

    dim3 grid(LL / TN, BB / TM);  // (16, 64) = 1024 CTAs
    rbf_fused<<<grid, 256, SMEM_SIZE>>>(x, lm, out);
}

// round 13
// speedup vs baseline: 1.6259x; 1.4629x over previous
#include <cuda_runtime.h>
#include <cuda_fp16.h>
#include <cstdint>

// ---------------------------------------------------------------------------
// RBF layer: out[b,l] = exp(-gamma * max(||x_b||^2 + ||lm_l||^2 - 2 x_b.lm_l, 0))
// B=8192, L=2048, D=256, gamma = 1/256.
// R13: revert to the measured-best R5 configuration (3-stage cp.async,
// fp32-accum HMMA, 32x64 warp tiles, 2 CTAs/SM) — every structural deviation
// regressed; mainloop sits at ~96% of the legacy mma.sync issue ceiling.
// Adds only: streaming (evict-first) output stores + hoisted epilogue
// addressing. fp16 inputs, exact fp32 norms, ex2 epilogue.
// ---------------------------------------------------------------------------

#define BB 8192
#define LL 2048
#define DD 256
#define TM 128
#define TN 128

// smem: 3 stages x (A 16KB + B 16KB) + l2 tile
#define STAGE_BYTES 32768
#define SMEM_L2     98304
#define SMEM_SIZE   98816

// ---------------- device scratch (static: no allocation APIs) --------------
__device__ __align__(16) __half g_xh[BB * DD];
__device__ __align__(16) __half g_lh[LL * DD];
__device__ float g_x2[BB];
__device__ float g_l2[LL];

// ---------------- helpers ---------------------------------------------------
__device__ __forceinline__ uint32_t smem_u32(const void* p) {
    uint32_t a;
    asm("{ .reg .u64 t; cvta.to.shared.u64 t, %1; cvt.u32.u64 %0, t; }"
        : "=r"(a) : "l"(p));
    return a;
}

__device__ __forceinline__ float fast_ex2(float x) {
    float y;
    asm("ex2.approx.ftz.f32 %0, %1;" : "=f"(y) : "f"(x));
    return y;
}

// streaming (evict-first) 8B store: output is write-once, never re-read
__device__ __forceinline__ void stg_cs_v2(float* p, float a, float b) {
    asm volatile("st.global.cs.v2.f32 [%0], {%1, %2};" ::
                 "l"(p), "f"(a), "f"(b) : "memory");
}

#define CP_ASYNC_16(sa, ga)                                               \
    asm volatile("cp.async.cg.shared.global [%0], [%1], 16;" ::           \
                 "r"(sa), "l"(ga))
#define CP_COMMIT() asm volatile("cp.async.commit_group;" ::: "memory")
#define CP_WAIT0()  asm volatile("cp.async.wait_group 0;" ::: "memory")
#define CP_WAIT1()  asm volatile("cp.async.wait_group 1;" ::: "memory")

#define LDSM4(r0, r1, r2, r3, addr)                                        \
    asm volatile("ldmatrix.sync.aligned.m8n8.x4.shared.b16 {%0,%1,%2,%3}, [%4];" \
                 : "=r"(r0), "=r"(r1), "=r"(r2), "=r"(r3) : "r"(addr))

#define MMA16816(d, a0, a1, a2, a3, b0, b1)                                \
    asm volatile(                                                          \
        "mma.sync.aligned.m16n8k16.row.col.f32.f16.f16.f32 "               \
        "{%0,%1,%2,%3}, {%4,%5,%6,%7}, {%8,%9}, {%0,%1,%2,%3};"            \
        : "+f"((d)[0]), "+f"((d)[1]), "+f"((d)[2]), "+f"((d)[3])           \
        : "r"(a0), "r"(a1), "r"(a2), "r"(a3), "r"(b0), "r"(b1))

// ---------------- prep: fp32 -> fp16 + exact fp32 row norms ----------------
__global__ void __launch_bounds__(256) rbf_prep(const float* __restrict__ x,
                                                const float* __restrict__ lm) {
    int warp = threadIdx.x >> 5, lane = threadIdx.x & 31;
    int row = blockIdx.x * 8 + warp;
    const float* src;
    __half* dst;
    float* nrm;
    if (row < BB) {
        src = x + (size_t)row * DD;
        dst = g_xh + (size_t)row * DD;
        nrm = g_x2 + row;
    } else {
        int r = row - BB;
        if (r >= LL) return;
        src = lm + (size_t)r * DD;
        dst = g_lh + (size_t)r * DD;
        nrm = g_l2 + r;
    }
    float4 a = *(const float4*)(src + lane * 8);
    float4 b = *(const float4*)(src + lane * 8 + 4);
    float s = a.x * a.x + a.y * a.y + a.z * a.z + a.w * a.w +
              b.x * b.x + b.y * b.y + b.z * b.z + b.w * b.w;
    __half2 h0 = __floats2half2_rn(a.x, a.y);
    __half2 h1 = __floats2half2_rn(a.z, a.w);
    __half2 h2 = __floats2half2_rn(b.x, b.y);
    __half2 h3 = __floats2half2_rn(b.z, b.w);
    uint4 u;
    u.x = reinterpret_cast<uint32_t&>(h0);
    u.y = reinterpret_cast<uint32_t&>(h1);
    u.z = reinterpret_cast<uint32_t&>(h2);
    u.w = reinterpret_cast<uint32_t&>(h3);
    *reinterpret_cast<uint4*>(dst + lane * 8) = u;
#pragma unroll
    for (int o = 16; o; o >>= 1) s += __shfl_xor_sync(0xffffffffu, s, o);
    if (lane == 0) *nrm = s;
}

// ---------------- main GEMM + exp epilogue ----------------------------------
__global__ void __launch_bounds__(256, 2) rbf_main(float* __restrict__ out) {
    extern __shared__ char smem[];
    uint32_t sb = smem_u32(smem);
    int tid = threadIdx.x, wid = tid >> 5, lane = tid & 31;
    int m0 = blockIdx.y * TM;
    int n0 = blockIdx.x * TN;
    int wm = (wid & 3) * 32;   // warp M offset within tile
    int wn = (wid >> 2) * 64;  // warp N offset within tile

    // landmark norm tile -> smem
    if (tid < TN)
        reinterpret_cast<float*>(smem + SMEM_L2)[tid] = g_l2[n0 + tid];

    // ---- cp.async prefetch of one K-chunk (64 halves) into stage kc%3 ----
    auto prefetch = [&](int kc) {
        int stage = kc % 3;
        uint32_t sA = sb + stage * STAGE_BYTES;
        uint32_t sB = sA + 16384;
        int koff = kc * 64;
#pragma unroll
        for (int j = 0; j < 4; j++) {
            int idx = tid + j * 256;       // 0..1023
            int r = idx >> 3, c = idx & 7; // row, 16B-chunk
            uint32_t soff = (uint32_t)(r * 128 + ((c * 16) ^ ((r & 7) << 4)));
            const __half* ga = g_xh + (size_t)(m0 + r) * DD + koff + c * 8;
            const __half* gb = g_lh + (size_t)(n0 + r) * DD + koff + c * 8;
            CP_ASYNC_16(sA + soff,
                        (unsigned long long)__cvta_generic_to_global((void*)ga));
            CP_ASYNC_16(sB + soff,
                        (unsigned long long)__cvta_generic_to_global((void*)gb));
        }
        CP_COMMIT();
    };

    float acc[2][8][4];
#pragma unroll
    for (int mt = 0; mt < 2; mt++)
#pragma unroll
        for (int nt = 0; nt < 8; nt++)
#pragma unroll
            for (int i = 0; i < 4; i++) acc[mt][nt][i] = 0.0f;

    // lane-level smem addressing (constant across k-steps)
    int la = lane & 15;
    uint32_t xm = (uint32_t)((lane & 7) << 4);
    uint32_t kblA = (uint32_t)(((lane >> 4) & 1) << 4);  // k8 select for A
    int rb = (lane & 7) + (((lane >> 4) & 1) << 3);      // B row within 16
    uint32_t kblB = (uint32_t)(((lane >> 3) & 1) << 4);  // k8 select for B

    // prefetch depth 2
    prefetch(0);
    prefetch(1);

#pragma unroll
    for (int kc = 0; kc < 4; kc++) {
        // stage kc must be complete; at kc<3 one newer group may stay in flight
        if (kc == 3) { CP_WAIT0(); } else { CP_WAIT1(); }
        __syncthreads();
        if (kc < 2) prefetch(kc + 2);

        int stage = kc % 3;
        uint32_t sA = sb + stage * STAGE_BYTES;
        uint32_t sB = sA + 16384;
        uint32_t aRow0 = sA + (uint32_t)((wm + la) * 128);
        uint32_t aRow1 = aRow0 + 16 * 128;
        uint32_t bRow = sB + (uint32_t)((wn + rb) * 128);

#pragma unroll
        for (int ks = 0; ks < 4; ks++) {
            uint32_t kb = (uint32_t)(ks * 32);
            uint32_t a0[4], a1[4];
            uint32_t adA = (kb + kblA) ^ xm;
            LDSM4(a0[0], a0[1], a0[2], a0[3], aRow0 + adA);
            LDSM4(a1[0], a1[1], a1[2], a1[3], aRow1 + adA);
            uint32_t bf[8][2];
            uint32_t adB = (kb + kblB) ^ xm;
#pragma unroll
            for (int ntp = 0; ntp < 4; ntp++) {
                uint32_t r0, r1, r2, r3;
                LDSM4(r0, r1, r2, r3, bRow + (uint32_t)(ntp * 2048) + adB);
                bf[2 * ntp][0] = r0; bf[2 * ntp][1] = r1;
                bf[2 * ntp + 1][0] = r2; bf[2 * ntp + 1][1] = r3;
            }
#pragma unroll
            for (int nt = 0; nt < 8; nt++) {
                MMA16816(acc[0][nt], a0[0], a0[1], a0[2], a0[3],
                         bf[nt][0], bf[nt][1]);
                MMA16816(acc[1][nt], a1[0], a1[1], a1[2], a1[3],
                         bf[nt][0], bf[nt][1]);
            }
        }
        // no trailing barrier: next iteration's top barrier protects stage reuse
    }

    // ---- epilogue: ex2(C * max(x2 + l2 - 2*cross, 0)),  C = -log2(e)/256 ----
    const float* l2t = reinterpret_cast<const float*>(smem + SMEM_L2);
    const float C = -1.44269504088896f / 256.0f;
    int qr = lane >> 2, qc = (lane & 3) << 1;
#pragma unroll
    for (int mt = 0; mt < 2; mt++) {
#pragma unroll
        for (int h = 0; h < 2; h++) {
            int row = m0 + wm + mt * 16 + h * 8 + qr;
            float x2v = __ldg(&g_x2[row]);
            float* obase = out + (size_t)row * LL + n0 + wn + qc;
#pragma unroll
            for (int nt = 0; nt < 8; nt++) {
                int col = nt * 8 + qc;
                float d0 = fmaxf(x2v + l2t[wn + col] -
                                 2.0f * acc[mt][nt][h * 2 + 0], 0.0f);
                float d1 = fmaxf(x2v + l2t[wn + col + 1] -
                                 2.0f * acc[mt][nt][h * 2 + 1], 0.0f);
                stg_cs_v2(obase + nt * 8, fast_ex2(C * d0), fast_ex2(C * d1));
            }
        }
    }
}

// ---------------- launch ----------------------------------------------------
extern "C" void kernel_launch(void* const* d_in, const int* in_sizes, int n_in,
                              void* d_out, int out_size) {
    const float* x = (const float*)d_in[0];   // [8192, 256]
    const float* lm = (const float*)d_in[1];  // [2048, 256]
    float* out = (float*)d_out;               // [8192, 2048]

    cudaFuncSetAttribute(rbf_main, cudaFuncAttributeMaxDynamicSharedMemorySize,
                         SMEM_SIZE);

    rbf_prep<<<(BB + LL) / 8, 256>>>(x, lm);
    dim3 grid(LL / TN, BB / TM);  // (16, 64) = 1024 CTAs
    rbf_main<<<grid, 256, SMEM_SIZE>>>(out);
}